// round 7
// baseline (speedup 1.0000x reference)
#include <cuda_runtime.h>
#include <cstdint>

#define B_  2
#define S_  2048
#define D_  1024
#define H_  16
#define HD_ 64
#define M_  (B_*S_)   // 4096

// ---------------------------------------------------------------------------
// Scratch (allocation-free rule: __device__ globals)
// ---------------------------------------------------------------------------
__device__ float g_q[B_*H_*S_*HD_];   // [b,h,s,hd]
__device__ float g_k[B_*H_*S_*HD_];
__device__ float g_v[B_*H_*S_*HD_];
__device__ float g_ao[M_*D_];         // attention out, [b,s, h*hd]
__device__ float g_wt[4*D_*D_];       // transposed weights [n][k]

// ---------------------------------------------------------------------------
__device__ __forceinline__ float to_tf32(float x) {
    uint32_t u;
    asm("cvt.rna.tf32.f32 %0, %1;" : "=r"(u) : "f"(x));
    return __uint_as_float(u);
}

__device__ __forceinline__ void mma_tf32(float* d, const uint32_t* a, const uint32_t* b) {
    asm volatile(
        "mma.sync.aligned.m16n8k8.row.col.f32.tf32.tf32.f32 "
        "{%0,%1,%2,%3}, {%4,%5,%6,%7}, {%8,%9}, {%0,%1,%2,%3};"
        : "+f"(d[0]), "+f"(d[1]), "+f"(d[2]), "+f"(d[3])
        : "r"(a[0]), "r"(a[1]), "r"(a[2]), "r"(a[3]), "r"(b[0]), "r"(b[1]));
}

// ---------------------------------------------------------------------------
// Weight transpose + tf32 round: dst[n][k] = tf32(src[k][n])
// ---------------------------------------------------------------------------
__global__ __launch_bounds__(256)
void transpose_kernel(const float* __restrict__ src, int widx)
{
    __shared__ float t[32][33];
    float* dst = g_wt + (size_t)widx * D_ * D_;
    int bx = blockIdx.x * 32, by = blockIdx.y * 32;
    int tx = threadIdx.x, ty = threadIdx.y;
    #pragma unroll
    for (int i = 0; i < 32; i += 8)
        t[ty + i][tx] = src[(size_t)(by + ty + i) * D_ + bx + tx];
    __syncthreads();
    #pragma unroll
    for (int i = 0; i < 32; i += 8)
        dst[(size_t)(bx + ty + i) * D_ + by + tx] = t[tx][ty + i];
}

// ---------------------------------------------------------------------------
// tf32 mma.sync GEMM (validated R4): C = A . Wt^T + bias
// ---------------------------------------------------------------------------
template<int MODE>
__global__ __launch_bounds__(256)
void gemm_mma_kernel(const float* __restrict__ Ap,
                     const float* __restrict__ bias,
                     float* __restrict__ outp)
{
    __shared__ float As[128][36];
    __shared__ float Bs[128][36];

    const int tid = threadIdx.x;
    const int wid = tid >> 5, lid = tid & 31;
    const int g = lid >> 2, tig = lid & 3;
    const int wm = (wid >> 2) * 64;
    const int wn = (wid & 3) * 32;
    const int bm = blockIdx.y * 128;
    const int bn = blockIdx.x * 128;

    const float* A  = (MODE == 0) ? (const float*)g_ao : Ap;
    const float* Bt = g_wt + (size_t)((MODE == 0) ? 3 : (MODE - 1)) * D_ * D_;

    float acc[4][4][4];
    #pragma unroll
    for (int mb = 0; mb < 4; mb++)
        #pragma unroll
        for (int nb = 0; nb < 4; nb++)
            #pragma unroll
            for (int i = 0; i < 4; i++) acc[mb][nb][i] = 0.f;

    for (int c = 0; c < D_ / 32; c++) {
        const int k0 = c * 32;
        #pragma unroll
        for (int i = 0; i < 4; i++) {
            int idx = tid + i * 256;
            int row = idx >> 3, v = (idx & 7) * 4;
            float4 av = *(const float4*)&A [(size_t)(bm + row) * D_ + k0 + v];
            float4 bv = *(const float4*)&Bt[(size_t)(bn + row) * D_ + k0 + v];
            av.x = to_tf32(av.x); av.y = to_tf32(av.y);
            av.z = to_tf32(av.z); av.w = to_tf32(av.w);
            *(float4*)&As[row][v] = av;
            *(float4*)&Bs[row][v] = bv;   // Bt already tf32-rounded
        }
        __syncthreads();

        #pragma unroll
        for (int ks = 0; ks < 4; ks++) {
            const int k = ks * 8;
            uint32_t af[4][4], bf[4][2];
            #pragma unroll
            for (int mb = 0; mb < 4; mb++) {
                int m = wm + mb * 16 + g;
                af[mb][0] = __float_as_uint(As[m    ][k + tig]);
                af[mb][1] = __float_as_uint(As[m + 8][k + tig]);
                af[mb][2] = __float_as_uint(As[m    ][k + tig + 4]);
                af[mb][3] = __float_as_uint(As[m + 8][k + tig + 4]);
            }
            #pragma unroll
            for (int nb = 0; nb < 4; nb++) {
                int n = wn + nb * 8 + g;
                bf[nb][0] = __float_as_uint(Bs[n][k + tig]);
                bf[nb][1] = __float_as_uint(Bs[n][k + tig + 4]);
            }
            #pragma unroll
            for (int mb = 0; mb < 4; mb++)
                #pragma unroll
                for (int nb = 0; nb < 4; nb++)
                    mma_tf32(acc[mb][nb], af[mb], bf[nb]);
        }
        __syncthreads();
    }

    float* qkv = (MODE == 1) ? g_q : (MODE == 2) ? g_k : g_v;
    #pragma unroll
    for (int mb = 0; mb < 4; mb++) {
        #pragma unroll
        for (int half = 0; half < 2; half++) {
            const int m = bm + wm + mb * 16 + g + half * 8;
            #pragma unroll
            for (int nb = 0; nb < 4; nb++) {
                const int n = bn + wn + nb * 8 + 2 * tig;
                float2 o;
                o.x = acc[mb][nb][half * 2 + 0] + __ldg(&bias[n]);
                o.y = acc[mb][nb][half * 2 + 1] + __ldg(&bias[n + 1]);
                if (MODE == 0) {
                    *(float2*)&outp[(size_t)m * D_ + n] = o;
                } else {
                    int b = m >> 11, s = m & 2047;
                    int h = n >> 6,  hd = n & 63;
                    *(float2*)&qkv[(((size_t)(b * H_ + h)) * S_ + s) * HD_ + hd] = o;
                }
            }
        }
    }
}

// ---------------------------------------------------------------------------
// Flash attention, tf32 mma, fragment-packed smem layouts.
// CTA: 128 q rows x full head; 8 warps, warp-local softmax (as R4).
// QF: [64 groups (w*8+j)][33] float4 — A-frag quad per lane, LDS.128.
// KF/VF: [64 groups (j*8+nb)][33] float2 — B-frag pair per lane, LDS.64.
// Ps: [128][68] float — unchanged (C->A relayout via smem).
// smem floats: QF 8448 + KF 4224 + VF 4224 + Ps 8704 = 25600 (100 KB).
// ---------------------------------------------------------------------------
#define ATT_SMEM (25600 * 4)

__global__ __launch_bounds__(256, 2)
void attn_mma_kernel()
{
    extern __shared__ float sm[];
    float4* QF = (float4*)sm;                 // [64][33] float4
    float2* KF = (float2*)(sm + 8448);        // [64][33] float2
    float2* VF = (float2*)(sm + 12672);       // [64][33] float2
    float*  Ps = sm + 16896;                  // [128][68]

    const int tid = threadIdx.x;
    const int wid = tid >> 5, lid = tid & 31;
    const int g = lid >> 2, tig = lid & 3;
    const int wq = wid * 16;
    const int bh = blockIdx.y;
    const int q0 = blockIdx.x * 128;

    const float* Qb = g_q + (size_t)bh * S_ * HD_;
    const float* Kb = g_k + (size_t)bh * S_ * HD_;
    const float* Vb = g_v + (size_t)bh * S_ * HD_;

    // ---- Q fill (once): element Q[r][c] -> QF[(r>>4)*8 + c>>3][4*(r&7)+(c&3)]
    //      component = ((c>>2)&1)*2 + ((r>>3)&1). Scaled by 1/8, tf32.
    #pragma unroll
    for (int it = 0; it < 4; it++) {
        int task = tid + it * 256;            // 1024 tasks: (r 0..127, j 0..7)
        int r = task >> 3, j = task & 7;
        float a0[4], a1[4];
        *(float4*)a0 = *(const float4*)&Qb[(size_t)(q0 + r) * HD_ + j * 8];
        *(float4*)a1 = *(const float4*)&Qb[(size_t)(q0 + r) * HD_ + j * 8 + 4];
        float* q4 = (float*)&QF[((r >> 4) * 8 + j) * 33 + 4 * (r & 7)];
        int half = (r >> 3) & 1;
        #pragma unroll
        for (int s = 0; s < 4; s++) {
            q4[s * 4 + half]     = to_tf32(a0[s] * 0.125f);
            q4[s * 4 + 2 + half] = to_tf32(a1[s] * 0.125f);
        }
    }

    float m_i[2] = {-1e30f, -1e30f}, l_i[2] = {0.f, 0.f};
    float acc[8][4];
    #pragma unroll
    for (int nb = 0; nb < 8; nb++)
        #pragma unroll
        for (int i = 0; i < 4; i++) acc[nb][i] = 0.f;

    // lane decode for K fill: j = bits{0,1,4}, gamma = bits{2,3}
    const int kf_j = (lid & 3) | ((lid >> 4) << 2);
    const int kf_gm = (lid >> 2) & 3;
    // lane decode for V fill: jj = bits{2,3,4}, tv = bits{0,1}; nb = wid
    const int vf_jj = ((lid >> 4) << 2) | ((lid >> 2) & 3);
    const int vf_tv = lid & 3;

    for (int t = 0; t < S_; t += 64) {
        __syncthreads();   // prev tile reads done
        // ---- K fill: K[r][c] -> KF[(c>>3)*8 + (r>>3)][4*(r&7)+(c&3)], comp=(c>>2)&1
        #pragma unroll
        for (int i = 0; i < 2; i++) {
            int r = (i * 8 + wid) * 4 + kf_gm;
            float k0[4], k1[4];
            *(float4*)k0 = *(const float4*)&Kb[(size_t)(t + r) * HD_ + kf_j * 8];
            *(float4*)k1 = *(const float4*)&Kb[(size_t)(t + r) * HD_ + kf_j * 8 + 4];
            float2* kd = &KF[(kf_j * 8 + (r >> 3)) * 33 + 4 * (r & 7)];
            #pragma unroll
            for (int s = 0; s < 4; s++)
                kd[s] = make_float2(to_tf32(k0[s]), to_tf32(k1[s]));
        }
        // ---- V fill: V[r][c] (r=kv, c=hd) -> VF[(r>>3)*8 + (c>>3)][4*(c&7)+(r&3)],
        //      comp=(r>>2)&1. Thread: rows (jj*8+tv, +4), cols wid*8..+7.
        {
            int r0 = vf_jj * 8 + vf_tv;
            float v0[4], v1[4], v2[4], v3[4];
            *(float4*)v0 = *(const float4*)&Vb[(size_t)(t + r0    ) * HD_ + wid * 8];
            *(float4*)v1 = *(const float4*)&Vb[(size_t)(t + r0    ) * HD_ + wid * 8 + 4];
            *(float4*)v2 = *(const float4*)&Vb[(size_t)(t + r0 + 4) * HD_ + wid * 8];
            *(float4*)v3 = *(const float4*)&Vb[(size_t)(t + r0 + 4) * HD_ + wid * 8 + 4];
            float2* vd = &VF[(vf_jj * 8 + wid) * 33 + vf_tv];
            #pragma unroll
            for (int s = 0; s < 4; s++) {
                vd[4 * s]       = make_float2(to_tf32(v0[s]), to_tf32(v2[s]));
                vd[4 * (s + 4)] = make_float2(to_tf32(v1[s]), to_tf32(v3[s]));
            }
        }
        __syncthreads();

        // ---- S = Q K^T
        float s[8][4];
        #pragma unroll
        for (int nb = 0; nb < 8; nb++)
            #pragma unroll
            for (int i = 0; i < 4; i++) s[nb][i] = 0.f;

        #pragma unroll
        for (int j = 0; j < 8; j++) {
            float4 aq = QF[(wid * 8 + j) * 33 + lid];
            const uint32_t* af = (const uint32_t*)&aq;
            #pragma unroll
            for (int nb = 0; nb < 8; nb++) {
                float2 bk = KF[(j * 8 + nb) * 33 + lid];
                mma_tf32(s[nb], af, (const uint32_t*)&bk);
            }
        }

        // ---- online softmax (rows wq+g, wq+g+8)
        float mx[2] = {-1e30f, -1e30f};
        #pragma unroll
        for (int nb = 0; nb < 8; nb++) {
            mx[0] = fmaxf(mx[0], fmaxf(s[nb][0], s[nb][1]));
            mx[1] = fmaxf(mx[1], fmaxf(s[nb][2], s[nb][3]));
        }
        #pragma unroll
        for (int h = 0; h < 2; h++) {
            mx[h] = fmaxf(mx[h], __shfl_xor_sync(0xffffffffu, mx[h], 1));
            mx[h] = fmaxf(mx[h], __shfl_xor_sync(0xffffffffu, mx[h], 2));
        }
        float mnew[2], al[2], rs[2] = {0.f, 0.f};
        #pragma unroll
        for (int h = 0; h < 2; h++) {
            mnew[h] = fmaxf(m_i[h], mx[h]);
            al[h] = __expf(m_i[h] - mnew[h]);
            m_i[h] = mnew[h];
        }
        #pragma unroll
        for (int nb = 0; nb < 8; nb++) {
            s[nb][0] = __expf(s[nb][0] - mnew[0]);
            s[nb][1] = __expf(s[nb][1] - mnew[0]);
            s[nb][2] = __expf(s[nb][2] - mnew[1]);
            s[nb][3] = __expf(s[nb][3] - mnew[1]);
            rs[0] += s[nb][0] + s[nb][1];
            rs[1] += s[nb][2] + s[nb][3];
        }
        #pragma unroll
        for (int h = 0; h < 2; h++) {
            rs[h] += __shfl_xor_sync(0xffffffffu, rs[h], 1);
            rs[h] += __shfl_xor_sync(0xffffffffu, rs[h], 2);
            l_i[h] = l_i[h] * al[h] + rs[h];
        }
        #pragma unroll
        for (int nb = 0; nb < 8; nb++) {
            acc[nb][0] *= al[0]; acc[nb][1] *= al[0];
            acc[nb][2] *= al[1]; acc[nb][3] *= al[1];
        }

        // ---- P -> warp-private smem (tf32)
        #pragma unroll
        for (int nb = 0; nb < 8; nb++) {
            float2 p0 = make_float2(to_tf32(s[nb][0]), to_tf32(s[nb][1]));
            float2 p1 = make_float2(to_tf32(s[nb][2]), to_tf32(s[nb][3]));
            *(float2*)&Ps[(wq + g    ) * 68 + nb * 8 + 2 * tig] = p0;
            *(float2*)&Ps[(wq + g + 8) * 68 + nb * 8 + 2 * tig] = p1;
        }
        __syncwarp();

        // ---- O += P V
        #pragma unroll
        for (int j = 0; j < 8; j++) {
            uint32_t af[4];
            af[0] = __float_as_uint(Ps[(wq + g    ) * 68 + j * 8 + tig]);
            af[1] = __float_as_uint(Ps[(wq + g + 8) * 68 + j * 8 + tig]);
            af[2] = __float_as_uint(Ps[(wq + g    ) * 68 + j * 8 + tig + 4]);
            af[3] = __float_as_uint(Ps[(wq + g + 8) * 68 + j * 8 + tig + 4]);
            #pragma unroll
            for (int nb = 0; nb < 8; nb++) {
                float2 bv = VF[(j * 8 + nb) * 33 + lid];
                mma_tf32(acc[nb], af, (const uint32_t*)&bv);
            }
        }
        __syncwarp();
    }

    // ---- epilogue
    const int bb = bh / H_, h = bh % H_;
    const float inv0 = 1.0f / l_i[0], inv1 = 1.0f / l_i[1];
    const int s0 = q0 + wq + g;
    #pragma unroll
    for (int nb = 0; nb < 8; nb++) {
        const int col = h * HD_ + nb * 8 + 2 * tig;
        float2 o0 = make_float2(acc[nb][0] * inv0, acc[nb][1] * inv0);
        float2 o1 = make_float2(acc[nb][2] * inv1, acc[nb][3] * inv1);
        *(float2*)&g_ao[(size_t)(bb * S_ + s0    ) * D_ + col] = o0;
        *(float2*)&g_ao[(size_t)(bb * S_ + s0 + 8) * D_ + col] = o1;
    }
}

// ---------------------------------------------------------------------------
extern "C" void kernel_launch(void* const* d_in, const int* in_sizes, int n_in,
                              void* d_out, int out_size)
{
    const float* x  = (const float*)d_in[0];
    const float* Wq = (const float*)d_in[1];
    const float* bq = (const float*)d_in[2];
    const float* Wk = (const float*)d_in[3];
    const float* bk = (const float*)d_in[4];
    const float* Wv = (const float*)d_in[5];
    const float* bv = (const float*)d_in[6];
    const float* Wo = (const float*)d_in[7];
    const float* bo = (const float*)d_in[8];
    float* out = (float*)d_out;

    static bool attr_done = false;
    if (!attr_done) {
        cudaFuncSetAttribute(attn_mma_kernel,
                             cudaFuncAttributeMaxDynamicSharedMemorySize, ATT_SMEM);
        attr_done = true;
    }

    dim3 gT(D_ / 32, D_ / 32);
    transpose_kernel<<<gT, dim3(32, 8)>>>(Wq, 0);
    transpose_kernel<<<gT, dim3(32, 8)>>>(Wk, 1);
    transpose_kernel<<<gT, dim3(32, 8)>>>(Wv, 2);
    transpose_kernel<<<gT, dim3(32, 8)>>>(Wo, 3);

    dim3 gG(D_ / 128, M_ / 128);   // (8, 32)
    gemm_mma_kernel<1><<<gG, 256>>>(x, bq, nullptr);
    gemm_mma_kernel<2><<<gG, 256>>>(x, bk, nullptr);
    gemm_mma_kernel<3><<<gG, 256>>>(x, bv, nullptr);

    dim3 gAttn(S_ / 128, B_ * H_);  // (16, 32)
    attn_mma_kernel<<<gAttn, 256, ATT_SMEM>>>();

    gemm_mma_kernel<0><<<gG, 256>>>(nullptr, bo, out);
}

// round 8
// speedup vs baseline: 1.0376x; 1.0376x over previous
#include <cuda_runtime.h>
#include <cstdint>

#define B_  2
#define S_  2048
#define D_  1024
#define H_  16
#define HD_ 64
#define M_  (B_*S_)   // 4096

// ---------------------------------------------------------------------------
// Scratch (allocation-free rule: __device__ globals)
// ---------------------------------------------------------------------------
__device__ float g_q[B_*H_*S_*HD_];   // [b,h,s,hd] tf32, Q pre-scaled
__device__ float g_k[B_*H_*S_*HD_];
__device__ float g_v[B_*H_*S_*HD_];
__device__ float g_ao[M_*D_];         // attention out (tf32-rounded)
__device__ float g_wt[4*D_*D_];       // transposed weights [n][k], tf32
__device__ float g_xr[M_*D_];         // x, tf32-rounded

// ---------------------------------------------------------------------------
__device__ __forceinline__ float to_tf32(float x) {
    uint32_t u;
    asm("cvt.rna.tf32.f32 %0, %1;" : "=r"(u) : "f"(x));
    return __uint_as_float(u);
}
__device__ __forceinline__ uint32_t smem_u32(const void* p) {
    uint32_t a;
    asm("{ .reg .u64 t; cvta.to.shared.u64 t, %1; cvt.u32.u64 %0, t; }" : "=r"(a) : "l"(p));
    return a;
}
__device__ __forceinline__ void cp16(void* smem_dst, const void* gmem_src) {
    asm volatile("cp.async.cg.shared.global [%0], [%1], 16;"
                 :: "r"(smem_u32(smem_dst)), "l"(gmem_src));
}
#define CP_COMMIT() asm volatile("cp.async.commit_group;" ::: "memory")
#define CP_WAIT0()  asm volatile("cp.async.wait_group 0;" ::: "memory")
#define CP_WAIT1()  asm volatile("cp.async.wait_group 1;" ::: "memory")

__device__ __forceinline__ void mma_tf32(float* d, const uint32_t* a, const uint32_t* b) {
    asm volatile(
        "mma.sync.aligned.m16n8k8.row.col.f32.tf32.tf32.f32 "
        "{%0,%1,%2,%3}, {%4,%5,%6,%7}, {%8,%9}, {%0,%1,%2,%3};"
        : "+f"(d[0]), "+f"(d[1]), "+f"(d[2]), "+f"(d[3])
        : "r"(a[0]), "r"(a[1]), "r"(a[2]), "r"(a[3]), "r"(b[0]), "r"(b[1]));
}

// ---------------------------------------------------------------------------
// x pre-round (RNA -> tf32-representable fp32)
// ---------------------------------------------------------------------------
__global__ __launch_bounds__(256)
void round_x_kernel(const float* __restrict__ x)
{
    size_t i = ((size_t)blockIdx.x * 256 + threadIdx.x) * 4;
    const size_t stride = (size_t)gridDim.x * 256 * 4;
    for (; i < (size_t)M_ * D_; i += stride) {
        float4 v = *(const float4*)&x[i];
        v.x = to_tf32(v.x); v.y = to_tf32(v.y);
        v.z = to_tf32(v.z); v.w = to_tf32(v.w);
        *(float4*)&g_xr[i] = v;
    }
}

// ---------------------------------------------------------------------------
// Fused weight transposes (+ tf32 round): z selects which W
// ---------------------------------------------------------------------------
__global__ __launch_bounds__(256)
void transpose_kernel(const float* __restrict__ w0, const float* __restrict__ w1,
                      const float* __restrict__ w2, const float* __restrict__ w3)
{
    __shared__ float t[32][33];
    const int z = blockIdx.z;
    const float* src = (z == 0) ? w0 : (z == 1) ? w1 : (z == 2) ? w2 : w3;
    float* dst = g_wt + (size_t)z * D_ * D_;
    int bx = blockIdx.x * 32, by = blockIdx.y * 32;
    int tx = threadIdx.x, ty = threadIdx.y;
    #pragma unroll
    for (int i = 0; i < 32; i += 8)
        t[ty + i][tx] = src[(size_t)(by + ty + i) * D_ + bx + tx];
    __syncthreads();
    #pragma unroll
    for (int i = 0; i < 32; i += 8)
        dst[(size_t)(bx + ty + i) * D_ + by + tx] = to_tf32(t[tx][ty + i]);
}

// ---------------------------------------------------------------------------
// cp.async double-buffered tf32 GEMM (R5-validated core, un-fused):
// C = A . Wt^T + bias.  CTA 128x128, 256 thr, 8 warps (2x4), K chunks of 32.
// MODE 1/2/3: A=g_xr -> g_q/g_k/g_v (tf32-rounded, Q pre-scaled 1/8)
// MODE 0:     A=g_ao -> outp (fp32)
// ---------------------------------------------------------------------------
#define GP 36
#define GBUF (128 * GP)
#define GEMM_SMEM (4 * GBUF * 4)   // 73728 B

template<int MODE>
__global__ __launch_bounds__(256)
void gemm_pipe_kernel(const float* __restrict__ bias,
                      float* __restrict__ outp)
{
    extern __shared__ float smf[];
    float* Asb[2] = { smf,          smf + GBUF };
    float* Bsb[2] = { smf + 2*GBUF, smf + 3*GBUF };

    const int tid = threadIdx.x;
    const int wid = tid >> 5, lid = tid & 31;
    const int g = lid >> 2, tig = lid & 3;
    const int wm = (wid >> 2) * 64;
    const int wn = (wid & 3) * 32;
    const int bm = blockIdx.y * 128;
    const int bn = blockIdx.x * 128;

    const float* A  = (MODE == 0) ? (const float*)g_ao : (const float*)g_xr;
    const float* Bt = g_wt + (size_t)((MODE == 0) ? 3 : (MODE - 1)) * D_ * D_;

    const int lrow = tid >> 3, lv = (tid & 7) * 4;

    float acc[4][4][4];
    #pragma unroll
    for (int mb = 0; mb < 4; mb++)
        #pragma unroll
        for (int nb = 0; nb < 4; nb++)
            #pragma unroll
            for (int i = 0; i < 4; i++) acc[mb][nb][i] = 0.f;

    {
        #pragma unroll
        for (int i = 0; i < 4; i++) {
            int row = lrow + i * 32;
            cp16(&Asb[0][row * GP + lv], &A [(size_t)(bm + row) * D_ + lv]);
            cp16(&Bsb[0][row * GP + lv], &Bt[(size_t)(bn + row) * D_ + lv]);
        }
        CP_COMMIT();
    }

    for (int c = 0; c < D_ / 32; c++) {
        const int cur = c & 1;
        if (c + 1 < D_ / 32) {
            const int k0 = (c + 1) * 32, nxt = cur ^ 1;
            #pragma unroll
            for (int i = 0; i < 4; i++) {
                int row = lrow + i * 32;
                cp16(&Asb[nxt][row * GP + lv], &A [(size_t)(bm + row) * D_ + k0 + lv]);
                cp16(&Bsb[nxt][row * GP + lv], &Bt[(size_t)(bn + row) * D_ + k0 + lv]);
            }
            CP_COMMIT();
            CP_WAIT1();
        } else {
            CP_WAIT0();
        }
        __syncthreads();

        const float* Ab = Asb[cur];
        const float* Bb = Bsb[cur];
        #pragma unroll
        for (int ks = 0; ks < 4; ks++) {
            const int k = ks * 8;
            uint32_t af[4][4], bf[4][2];
            #pragma unroll
            for (int mb = 0; mb < 4; mb++) {
                int m = wm + mb * 16 + g;
                af[mb][0] = __float_as_uint(Ab[(m    ) * GP + k + tig]);
                af[mb][1] = __float_as_uint(Ab[(m + 8) * GP + k + tig]);
                af[mb][2] = __float_as_uint(Ab[(m    ) * GP + k + tig + 4]);
                af[mb][3] = __float_as_uint(Ab[(m + 8) * GP + k + tig + 4]);
            }
            #pragma unroll
            for (int nb = 0; nb < 4; nb++) {
                int n = wn + nb * 8 + g;
                bf[nb][0] = __float_as_uint(Bb[n * GP + k + tig]);
                bf[nb][1] = __float_as_uint(Bb[n * GP + k + tig + 4]);
            }
            #pragma unroll
            for (int mb = 0; mb < 4; mb++)
                #pragma unroll
                for (int nb = 0; nb < 4; nb++)
                    mma_tf32(acc[mb][nb], af[mb], bf[nb]);
        }
        __syncthreads();
    }

    #pragma unroll
    for (int mb = 0; mb < 4; mb++) {
        #pragma unroll
        for (int half = 0; half < 2; half++) {
            const int m = bm + wm + mb * 16 + g + half * 8;
            #pragma unroll
            for (int nb = 0; nb < 4; nb++) {
                const int n = bn + wn + nb * 8 + 2 * tig;
                if (MODE == 0) {
                    float2 o;
                    o.x = acc[mb][nb][half * 2 + 0] + __ldg(&bias[n]);
                    o.y = acc[mb][nb][half * 2 + 1] + __ldg(&bias[n + 1]);
                    *(float2*)&outp[(size_t)m * D_ + n] = o;
                } else {
                    const float scale = (MODE == 1) ? 0.125f : 1.0f;
                    float* dst = (MODE == 1) ? g_q : (MODE == 2) ? g_k : g_v;
                    int b = m >> 11, s = m & 2047;
                    int h = n >> 6,  hd = n & 63;
                    float2 o;
                    o.x = to_tf32((acc[mb][nb][half * 2 + 0] + __ldg(&bias[n]))     * scale);
                    o.y = to_tf32((acc[mb][nb][half * 2 + 1] + __ldg(&bias[n + 1])) * scale);
                    *(float2*)&dst[(((size_t)(b * H_ + h)) * S_ + s) * HD_ + hd] = o;
                }
            }
        }
    }
}

// ---------------------------------------------------------------------------
// Flash attention, tf32 mma — R4-validated hot loop, verbatim.
// Inputs pre-rounded (Q pre-scaled) so fills store raw.
// Epilogue rounds g_ao to tf32 (validated in R5: rel_err unchanged).
// ---------------------------------------------------------------------------
#define AP 68
#define ATT_SMEM (384 * AP * 4)

__global__ __launch_bounds__(256, 2)
void attn_mma_kernel()
{
    extern __shared__ float sm[];
    float* Qs = sm;                 // [128][AP]
    float* Ks = sm + 128 * AP;      // [64][AP]
    float* Vt = sm + 192 * AP;      // [64][AP]  (hd x kv)
    float* Ps = sm + 256 * AP;      // [128][AP]

    const int tid = threadIdx.x;
    const int wid = tid >> 5, lid = tid & 31;
    const int g = lid >> 2, tig = lid & 3;
    const int wq = wid * 16;
    const int bh = blockIdx.y;
    const int q0 = blockIdx.x * 128;

    const float* Qb = g_q + (size_t)bh * S_ * HD_;
    const float* Kb = g_k + (size_t)bh * S_ * HD_;
    const float* Vb = g_v + (size_t)bh * S_ * HD_;

    #pragma unroll
    for (int i = 0; i < 8; i++) {
        int idx = tid + i * 256;
        int r = idx >> 4, c4 = (idx & 15) * 4;
        *(float4*)&Qs[r * AP + c4] = *(const float4*)&Qb[(size_t)(q0 + r) * HD_ + c4];
    }

    float m_i[2] = {-1e30f, -1e30f}, l_i[2] = {0.f, 0.f};
    float acc[8][4];
    #pragma unroll
    for (int nb = 0; nb < 8; nb++)
        #pragma unroll
        for (int i = 0; i < 4; i++) acc[nb][i] = 0.f;

    for (int t = 0; t < S_; t += 64) {
        __syncthreads();
        #pragma unroll
        for (int i = 0; i < 4; i++) {
            int idx = tid + i * 256;
            int r = idx >> 4, c4 = (idx & 15) * 4;
            *(float4*)&Ks[r * AP + c4] = *(const float4*)&Kb[(size_t)(t + r) * HD_ + c4];
        }
        #pragma unroll
        for (int i = 0; i < 4; i++) {
            int idx = tid + i * 256;
            int r = (idx >> 1) & 63;
            int c4 = ((idx & 1) | ((idx >> 7) << 1)) * 4;
            float4 vv = *(const float4*)&Vb[(size_t)(t + r) * HD_ + c4];
            Vt[(c4 + 0) * AP + r] = vv.x;
            Vt[(c4 + 1) * AP + r] = vv.y;
            Vt[(c4 + 2) * AP + r] = vv.z;
            Vt[(c4 + 3) * AP + r] = vv.w;
        }
        __syncthreads();

        float s[8][4];
        #pragma unroll
        for (int nb = 0; nb < 8; nb++)
            #pragma unroll
            for (int i = 0; i < 4; i++) s[nb][i] = 0.f;

        #pragma unroll
        for (int kk = 0; kk < 64; kk += 8) {
            uint32_t af[4];
            af[0] = __float_as_uint(Qs[(wq + g    ) * AP + kk + tig]);
            af[1] = __float_as_uint(Qs[(wq + g + 8) * AP + kk + tig]);
            af[2] = __float_as_uint(Qs[(wq + g    ) * AP + kk + tig + 4]);
            af[3] = __float_as_uint(Qs[(wq + g + 8) * AP + kk + tig + 4]);
            #pragma unroll
            for (int nb = 0; nb < 8; nb++) {
                uint32_t bf[2];
                bf[0] = __float_as_uint(Ks[(nb * 8 + g) * AP + kk + tig]);
                bf[1] = __float_as_uint(Ks[(nb * 8 + g) * AP + kk + tig + 4]);
                mma_tf32(s[nb], af, bf);
            }
        }

        float mx[2] = {-1e30f, -1e30f};
        #pragma unroll
        for (int nb = 0; nb < 8; nb++) {
            mx[0] = fmaxf(mx[0], fmaxf(s[nb][0], s[nb][1]));
            mx[1] = fmaxf(mx[1], fmaxf(s[nb][2], s[nb][3]));
        }
        #pragma unroll
        for (int h = 0; h < 2; h++) {
            mx[h] = fmaxf(mx[h], __shfl_xor_sync(0xffffffffu, mx[h], 1));
            mx[h] = fmaxf(mx[h], __shfl_xor_sync(0xffffffffu, mx[h], 2));
        }
        float mnew[2], al[2], rs[2] = {0.f, 0.f};
        #pragma unroll
        for (int h = 0; h < 2; h++) {
            mnew[h] = fmaxf(m_i[h], mx[h]);
            al[h] = __expf(m_i[h] - mnew[h]);
            m_i[h] = mnew[h];
        }
        #pragma unroll
        for (int nb = 0; nb < 8; nb++) {
            s[nb][0] = __expf(s[nb][0] - mnew[0]);
            s[nb][1] = __expf(s[nb][1] - mnew[0]);
            s[nb][2] = __expf(s[nb][2] - mnew[1]);
            s[nb][3] = __expf(s[nb][3] - mnew[1]);
            rs[0] += s[nb][0] + s[nb][1];
            rs[1] += s[nb][2] + s[nb][3];
        }
        #pragma unroll
        for (int h = 0; h < 2; h++) {
            rs[h] += __shfl_xor_sync(0xffffffffu, rs[h], 1);
            rs[h] += __shfl_xor_sync(0xffffffffu, rs[h], 2);
            l_i[h] = l_i[h] * al[h] + rs[h];
        }
        #pragma unroll
        for (int nb = 0; nb < 8; nb++) {
            acc[nb][0] *= al[0]; acc[nb][1] *= al[0];
            acc[nb][2] *= al[1]; acc[nb][3] *= al[1];
        }

        #pragma unroll
        for (int nb = 0; nb < 8; nb++) {
            float2 p0 = make_float2(to_tf32(s[nb][0]), to_tf32(s[nb][1]));
            float2 p1 = make_float2(to_tf32(s[nb][2]), to_tf32(s[nb][3]));
            *(float2*)&Ps[(wq + g    ) * AP + nb * 8 + 2 * tig] = p0;
            *(float2*)&Ps[(wq + g + 8) * AP + nb * 8 + 2 * tig] = p1;
        }
        __syncwarp();

        #pragma unroll
        for (int kk = 0; kk < 64; kk += 8) {
            uint32_t af[4];
            af[0] = __float_as_uint(Ps[(wq + g    ) * AP + kk + tig]);
            af[1] = __float_as_uint(Ps[(wq + g + 8) * AP + kk + tig]);
            af[2] = __float_as_uint(Ps[(wq + g    ) * AP + kk + tig + 4]);
            af[3] = __float_as_uint(Ps[(wq + g + 8) * AP + kk + tig + 4]);
            #pragma unroll
            for (int nb = 0; nb < 8; nb++) {
                uint32_t bf[2];
                bf[0] = __float_as_uint(Vt[(nb * 8 + g) * AP + kk + tig]);
                bf[1] = __float_as_uint(Vt[(nb * 8 + g) * AP + kk + tig + 4]);
                mma_tf32(acc[nb], af, bf);
            }
        }
        __syncwarp();
    }

    const int bb = bh / H_, h = bh % H_;
    const float inv0 = 1.0f / l_i[0], inv1 = 1.0f / l_i[1];
    const int s0 = q0 + wq + g;
    #pragma unroll
    for (int nb = 0; nb < 8; nb++) {
        const int col = h * HD_ + nb * 8 + 2 * tig;
        float2 o0 = make_float2(to_tf32(acc[nb][0] * inv0), to_tf32(acc[nb][1] * inv0));
        float2 o1 = make_float2(to_tf32(acc[nb][2] * inv1), to_tf32(acc[nb][3] * inv1));
        *(float2*)&g_ao[(size_t)(bb * S_ + s0    ) * D_ + col] = o0;
        *(float2*)&g_ao[(size_t)(bb * S_ + s0 + 8) * D_ + col] = o1;
    }
}

// ---------------------------------------------------------------------------
extern "C" void kernel_launch(void* const* d_in, const int* in_sizes, int n_in,
                              void* d_out, int out_size)
{
    const float* x  = (const float*)d_in[0];
    const float* Wq = (const float*)d_in[1];
    const float* bq = (const float*)d_in[2];
    const float* Wk = (const float*)d_in[3];
    const float* bk = (const float*)d_in[4];
    const float* Wv = (const float*)d_in[5];
    const float* bv = (const float*)d_in[6];
    const float* Wo = (const float*)d_in[7];
    const float* bo = (const float*)d_in[8];
    float* out = (float*)d_out;

    static bool attr_done = false;
    if (!attr_done) {
        cudaFuncSetAttribute(attn_mma_kernel,
                             cudaFuncAttributeMaxDynamicSharedMemorySize, ATT_SMEM);
        cudaFuncSetAttribute(gemm_pipe_kernel<0>,
                             cudaFuncAttributeMaxDynamicSharedMemorySize, GEMM_SMEM);
        cudaFuncSetAttribute(gemm_pipe_kernel<1>,
                             cudaFuncAttributeMaxDynamicSharedMemorySize, GEMM_SMEM);
        cudaFuncSetAttribute(gemm_pipe_kernel<2>,
                             cudaFuncAttributeMaxDynamicSharedMemorySize, GEMM_SMEM);
        cudaFuncSetAttribute(gemm_pipe_kernel<3>,
                             cudaFuncAttributeMaxDynamicSharedMemorySize, GEMM_SMEM);
        attr_done = true;
    }

    round_x_kernel<<<1024, 256>>>(x);
    dim3 gT(D_ / 32, D_ / 32, 4);
    transpose_kernel<<<gT, dim3(32, 8)>>>(Wq, Wk, Wv, Wo);

    dim3 gG(D_ / 128, M_ / 128);   // (8, 32)
    gemm_pipe_kernel<1><<<gG, 256, GEMM_SMEM>>>(bq, nullptr);
    gemm_pipe_kernel<2><<<gG, 256, GEMM_SMEM>>>(bk, nullptr);
    gemm_pipe_kernel<3><<<gG, 256, GEMM_SMEM>>>(bv, nullptr);

    dim3 gAttn(S_ / 128, B_ * H_);  // (16, 32)
    attn_mma_kernel<<<gAttn, 256, ATT_SMEM>>>();

    gemm_pipe_kernel<0><<<gG, 256, GEMM_SMEM>>>(bo, out);
}